// round 8
// baseline (speedup 1.0000x reference)
#include <cuda_runtime.h>
#include <cuda_bf16.h>
#include <cstdint>

#define BB 32
#define SS 512
#define DD 1024

// ---- device scratch (module-load allocated; no runtime allocs) ----
// E interleaved: [row][kc(32)][hi/lo][32 bf16]  (128B per kc per row)
__device__ unsigned short g_ei[(size_t)BB * SS * 2 * DD];   // 64 MB
// aspect copies: [b][buf(4: hi-p0, hi-p1, lo-p0, lo-p1)][2048 u16]
__device__ unsigned short g_asp[BB * 4 * 2048];             // 512 KB

// ============================ helpers ============================
__device__ __forceinline__ uint32_t smem_u32(const void* p) {
    uint32_t a;
    asm("{ .reg .u64 t; cvta.to.shared.u64 t, %1; cvt.u32.u64 %0, t; }" : "=r"(a) : "l"(p));
    return a;
}
__device__ __forceinline__ void cpasync16(uint32_t dst, const void* src) {
    asm volatile("cp.async.cg.shared.global [%0], [%1], 16;" :: "r"(dst), "l"(src));
}
__device__ __forceinline__ void ldsm4(uint32_t* r, uint32_t a) {
    asm volatile("ldmatrix.sync.aligned.m8n8.x4.shared.b16 {%0,%1,%2,%3}, [%4];"
                 : "=r"(r[0]), "=r"(r[1]), "=r"(r[2]), "=r"(r[3]) : "r"(a));
}
__device__ __forceinline__ void mma16816(float* c, const uint32_t* a, const uint32_t* b) {
    asm volatile(
        "mma.sync.aligned.m16n8k16.row.col.f32.bf16.bf16.f32 "
        "{%0,%1,%2,%3}, {%4,%5,%6,%7}, {%8,%9}, {%0,%1,%2,%3};"
        : "+f"(c[0]), "+f"(c[1]), "+f"(c[2]), "+f"(c[3])
        : "r"(a[0]), "r"(a[1]), "r"(a[2]), "r"(a[3]), "r"(b[0]), "r"(b[1]));
}
__device__ __forceinline__ uint32_t lds32(uint32_t a) {
    uint32_t v;
    asm volatile("ld.shared.b32 %0, [%1];" : "=r"(v) : "r"(a));
    return v;
}
__device__ __forceinline__ void sts32(uint32_t a, uint32_t v) {
    asm volatile("st.shared.b32 [%0], %1;" :: "r"(a), "r"(v));
}

// ============================ prep kernels ============================
__global__ void anorm_kernel(const float* __restrict__ a) {
    int b = blockIdx.x, t = threadIdx.x;  // 256 threads
    float4 v = ((const float4*)(a + (size_t)b * DD))[t];
    float sum = v.x * v.x + v.y * v.y + v.z * v.z + v.w * v.w;
    #pragma unroll
    for (int o = 16; o; o >>= 1) sum += __shfl_xor_sync(0xffffffffu, sum, o);
    __shared__ float ws[8];
    __shared__ float s_inv;
    if ((t & 31) == 0) ws[t >> 5] = sum;
    __syncthreads();
    if (t == 0) {
        float tot = 0.f;
        #pragma unroll
        for (int i = 0; i < 8; i++) tot += ws[i];
        s_inv = (tot > 0.f) ? rsqrtf(tot) : 0.f;
    }
    __syncthreads();
    float inv = s_inv;
    float n[4] = {v.x * inv, v.y * inv, v.z * inv, v.w * inv};
    unsigned short* base = g_asp + b * 4 * 2048;
    #pragma unroll
    for (int j = 0; j < 4; j++) {
        __nv_bfloat16 h = __float2bfloat16(n[j]);
        __nv_bfloat16 l = __float2bfloat16(n[j] - __bfloat162float(h));
        unsigned short hu = __bfloat16_as_ushort(h);
        unsigned short lu = __bfloat16_as_ushort(l);
        int e = 4 * t + j;
        base[e] = hu;                      base[e + 1024] = hu;
        base[2048 + ((e + 1023) & 2047)] = hu;
        base[2048 + ((e + 2047) & 2047)] = hu;
        base[4096 + e] = lu;               base[4096 + e + 1024] = lu;
        base[6144 + ((e + 1023) & 2047)] = lu;
        base[6144 + ((e + 2047) & 2047)] = lu;
    }
}

__global__ void esplit_kernel(const float* __restrict__ e) {
    int b = blockIdx.y, s = blockIdx.x, t = threadIdx.x;  // 256 threads
    size_t row = (size_t)b * SS + s;
    float4 v = ((const float4*)(e + row * DD))[t];
    float sum = v.x * v.x + v.y * v.y + v.z * v.z + v.w * v.w;
    #pragma unroll
    for (int o = 16; o; o >>= 1) sum += __shfl_xor_sync(0xffffffffu, sum, o);
    __shared__ float ws[8];
    __shared__ float s_inv;
    if ((t & 31) == 0) ws[t >> 5] = sum;
    __syncthreads();
    if (t == 0) {
        float tot = 0.f;
        #pragma unroll
        for (int i = 0; i < 8; i++) tot += ws[i];
        s_inv = (tot > 0.f) ? rsqrtf(tot) : 0.f;
    }
    __syncthreads();
    float inv = s_inv;
    float n[4] = {v.x * inv, v.y * inv, v.z * inv, v.w * inv};
    ushort4 ph, pl;
    unsigned short* hp = &ph.x;
    unsigned short* lp = &pl.x;
    #pragma unroll
    for (int j = 0; j < 4; j++) {
        __nv_bfloat16 h = __float2bfloat16(n[j]);
        __nv_bfloat16 l = __float2bfloat16(n[j] - __bfloat162float(h));
        hp[j] = __bfloat16_as_ushort(h);
        lp[j] = __bfloat16_as_ushort(l);
    }
    int kc = t >> 3, pos = (t & 7) * 4;
    size_t base = row * 2048 + (size_t)kc * 64 + pos;    // u16 units
    *((ushort4*)(g_ei + base)) = ph;
    *((ushort4*)(g_ei + base + 32)) = pl;
}

// ============================ GEMM kernel ============================
// out[b, s_base+m, i_base+n] = sum_k E[m][k] * Circ[n][k]   (3-way bf16 split)
// CTA 256x128, 256 thr (8 warps, warp 64x64), k-chunk 64, 2-stage A ring,
// B built in smem from aspect.
#define ROWB 272                 // 256B payload + 16B pad
#define ASTG (256 * ROWB)        // 69632 per A stage
#define BSTG (128 * ROWB)        // 34816 per B buffer
#define OFF_B (2 * ASTG)         // 139264
#define OFF_ASP (OFF_B + 2 * BSTG)   // 208896
#define SMEM_DYN (OFF_ASP + 16384)   // 225280
#define NCHUNK 16                // 1024 / 64

__global__ void __launch_bounds__(256, 1) gemm_kernel(float* __restrict__ out) {
    extern __shared__ __align__(128) char smem[];
    const uint32_t sbase = smem_u32(smem);
    const uint32_t sB = sbase + OFF_B;
    const uint32_t sAsp = sbase + OFF_ASP;

    const int b      = blockIdx.z;
    const int i_base = blockIdx.x * 128;
    const int s_base = blockIdx.y * 256;
    const int tid  = threadIdx.x;
    const int wid  = tid >> 5;
    const int lane = tid & 31;
    const int wm = wid & 3;      // 4 m-groups of 64
    const int wn = wid >> 2;     // 2 n-groups of 64

    // A loader: thread covers rows r0+16*i (i=0..15), fixed 16B segment tid&15
    const int r0  = tid >> 4;    // 0..15
    const int seg = tid & 15;
    const char* pA = (const char*)g_ei + ((size_t)b * SS + s_base + r0) * 4096 + seg * 16;
    const uint32_t drowA = sbase + (uint32_t)r0 * ROWB + seg * 16;

    // ldmatrix lane offsets
    const uint32_t a_lane = (uint32_t)(wm * 64 + (lane & 15)) * ROWB + (lane >> 4) * 16;
    const uint32_t b_lane = (uint32_t)(wn * 64 + (lane & 7) + 8 * (lane >> 4)) * ROWB
                          + ((lane >> 3) & 1) * 16;

    // B build: this warp owns rows bn0..bn0+15
    const int bn0 = wid * 16;

    float acc[4][8][4];
    #pragma unroll
    for (int mt = 0; mt < 4; mt++)
        #pragma unroll
        for (int nt = 0; nt < 8; nt++)
            #pragma unroll
            for (int j = 0; j < 4; j++) acc[mt][nt][j] = 0.f;

    #define LOAD_A(ST, KC) do {                                         \
        uint32_t so_ = (ST) * ASTG;                                     \
        size_t go_ = (size_t)(KC) * 256;                                \
        _Pragma("unroll")                                               \
        for (int i_ = 0; i_ < 16; i_++)                                 \
            cpasync16(drowA + so_ + i_ * (16 * ROWB),                   \
                      pA + go_ + (size_t)i_ * (16 * 4096));             \
        asm volatile("cp.async.commit_group;");                         \
    } while (0)

    // build 4 B rows (rr base RB) for chunk CN into buffer CN&1
    #define BUILD_B4(CN, RB) do {                                       \
        uint32_t bb_ = sB + ((CN) & 1) * BSTG;                          \
        int k0_ = (CN) * 64;                                            \
        _Pragma("unroll")                                               \
        for (int rr_ = (RB); rr_ < (RB) + 4; rr_++) {                   \
            int row_ = bn0 + rr_;                                       \
            int ig_ = i_base + row_;                                    \
            int p_ = ig_ & 1;                                           \
            uint32_t su_ = (uint32_t)((DD + k0_ - ig_ - p_) >> 1) * 4 + lane * 4; \
            uint32_t dst_ = bb_ + (uint32_t)row_ * ROWB + lane * 4;     \
            sts32(dst_, lds32(sAsp + p_ * 4096 + su_));                 \
            sts32(dst_ + 128, lds32(sAsp + (2 + p_) * 4096 + su_));     \
        }                                                               \
    } while (0)

    // ---- prologue: aspect copies + A(0) in one group ----
    {
        const char* pAsp = (const char*)(g_asp + b * 4 * 2048);
        #pragma unroll
        for (int i = 0; i < 4; i++)
            cpasync16(sAsp + (tid + 256 * i) * 16, pAsp + (size_t)(tid + 256 * i) * 16);
    }
    LOAD_A(0, 0);

    asm volatile("cp.async.wait_group 0;" ::: "memory");
    __syncthreads();
    BUILD_B4(0, 0); BUILD_B4(0, 4); BUILD_B4(0, 8); BUILD_B4(0, 12);

    #pragma unroll 2
    for (int c = 0; c < NCHUNK; c++) {
        if (c > 0) {
            asm volatile("cp.async.wait_group 0;" ::: "memory");
            __syncthreads();
        }
        if (c + 1 < NCHUNK) LOAD_A((c + 1) & 1, c + 1);

        const uint32_t sa = sbase + (c & 1) * ASTG;
        const uint32_t sb = sB + (c & 1) * BSTG;
        const bool more = (c + 1 < NCHUNK);

        #pragma unroll
        for (int kk = 0; kk < 4; kk++) {
            // A layout per 256B: [kc0 hi64|kc0 lo64|kc1 hi64|kc1 lo64]
            const uint32_t akb = (uint32_t)((kk >> 1) * 128 + (kk & 1) * 32);
            // B layout per 256B: [hi 128 | lo 128]
            const uint32_t bkb = (uint32_t)(kk * 32);
            uint32_t aH[4][4], aL[4][4], bH[4][4], bL[4][4];
            #pragma unroll
            for (int mt = 0; mt < 4; mt++)
                ldsm4(aH[mt], sa + a_lane + mt * 16 * ROWB + akb);
            #pragma unroll
            for (int p = 0; p < 4; p++)
                ldsm4(bH[p], sb + b_lane + p * 16 * ROWB + bkb);
            #pragma unroll
            for (int p = 0; p < 4; p++)
                ldsm4(bL[p], sb + b_lane + p * 16 * ROWB + bkb + 128);
            #pragma unroll
            for (int mt = 0; mt < 4; mt++)
                #pragma unroll
                for (int nt = 0; nt < 8; nt++)
                    mma16816(acc[mt][nt], aH[mt], &bH[nt >> 1][2 * (nt & 1)]);
            // interleave B-build for next chunk (4 rows per kk step)
            if (more) BUILD_B4(c + 1, kk * 4);
            #pragma unroll
            for (int mt = 0; mt < 4; mt++)
                #pragma unroll
                for (int nt = 0; nt < 8; nt++)
                    mma16816(acc[mt][nt], aH[mt], &bL[nt >> 1][2 * (nt & 1)]);
            #pragma unroll
            for (int mt = 0; mt < 4; mt++)
                ldsm4(aL[mt], sa + a_lane + mt * 16 * ROWB + akb + 64);
            #pragma unroll
            for (int mt = 0; mt < 4; mt++)
                #pragma unroll
                for (int nt = 0; nt < 8; nt++)
                    mma16816(acc[mt][nt], aL[mt], &bH[nt >> 1][2 * (nt & 1)]);
        }
    }

    // ---- epilogue: direct f32 stores ----
    #pragma unroll
    for (int mt = 0; mt < 4; mt++) {
        int rr = s_base + wm * 64 + mt * 16 + (lane >> 2);
        float* p0 = out + ((size_t)b * SS + rr) * DD + i_base + wn * 64 + (lane & 3) * 2;
        float* p1 = p0 + (size_t)8 * DD;
        #pragma unroll
        for (int nt = 0; nt < 8; nt++) {
            *(float2*)(p0 + nt * 8) = make_float2(acc[mt][nt][0], acc[mt][nt][1]);
            *(float2*)(p1 + nt * 8) = make_float2(acc[mt][nt][2], acc[mt][nt][3]);
        }
    }
}

// ============================ launch ============================
extern "C" void kernel_launch(void* const* d_in, const int* in_sizes, int n_in,
                              void* d_out, int out_size) {
    const float* emb = (const float*)d_in[0];   // (32, 512, 1024) f32
    const float* asp = (const float*)d_in[1];   // (32, 1024) f32
    float* out = (float*)d_out;                 // (32, 512, 1024) f32

    cudaFuncSetAttribute(gemm_kernel, cudaFuncAttributeMaxDynamicSharedMemorySize, SMEM_DYN);

    anorm_kernel<<<BB, 256>>>(asp);
    esplit_kernel<<<dim3(SS, BB), 256>>>(emb);
    gemm_kernel<<<dim3(DD / 128, SS / 256, BB), 256, SMEM_DYN>>>(out);
}

// round 9
// speedup vs baseline: 1.4661x; 1.4661x over previous
#include <cuda_runtime.h>
#include <cuda_fp16.h>
#include <cstdint>

#define BB 32
#define SS 512
#define DD 1024

// ---- device scratch (module-load allocated; no runtime allocs) ----
// E normalized fp16: [row][k] contiguous (2048B per row)
__device__ unsigned short g_eh[(size_t)BB * SS * DD];       // 32 MB
// aspect copies fp16: [b][buf(4: hi-p0, hi-p1, lo-p0, lo-p1)][2048 u16]
__device__ unsigned short g_asp[BB * 4 * 2048];             // 512 KB

// ============================ helpers ============================
__device__ __forceinline__ uint32_t smem_u32(const void* p) {
    uint32_t a;
    asm("{ .reg .u64 t; cvta.to.shared.u64 t, %1; cvt.u32.u64 %0, t; }" : "=r"(a) : "l"(p));
    return a;
}
__device__ __forceinline__ void cpasync16(uint32_t dst, const void* src) {
    asm volatile("cp.async.cg.shared.global [%0], [%1], 16;" :: "r"(dst), "l"(src));
}
__device__ __forceinline__ void ldsm4(uint32_t* r, uint32_t a) {
    asm volatile("ldmatrix.sync.aligned.m8n8.x4.shared.b16 {%0,%1,%2,%3}, [%4];"
                 : "=r"(r[0]), "=r"(r[1]), "=r"(r[2]), "=r"(r[3]) : "r"(a));
}
__device__ __forceinline__ void mma16816(float* c, const uint32_t* a, const uint32_t* b) {
    asm volatile(
        "mma.sync.aligned.m16n8k16.row.col.f32.f16.f16.f32 "
        "{%0,%1,%2,%3}, {%4,%5,%6,%7}, {%8,%9}, {%0,%1,%2,%3};"
        : "+f"(c[0]), "+f"(c[1]), "+f"(c[2]), "+f"(c[3])
        : "r"(a[0]), "r"(a[1]), "r"(a[2]), "r"(a[3]), "r"(b[0]), "r"(b[1]));
}
__device__ __forceinline__ uint32_t lds32(uint32_t a) {
    uint32_t v;
    asm volatile("ld.shared.b32 %0, [%1];" : "=r"(v) : "r"(a));
    return v;
}
__device__ __forceinline__ void sts32(uint32_t a, uint32_t v) {
    asm volatile("st.shared.b32 [%0], %1;" :: "r"(a), "r"(v));
}

// ============================ prep kernels ============================
// normalize aspect, split hi/lo fp16, write 4 parity copies
__global__ void anorm_kernel(const float* __restrict__ a) {
    int b = blockIdx.x, t = threadIdx.x;  // 256 threads
    float4 v = ((const float4*)(a + (size_t)b * DD))[t];
    float sum = v.x * v.x + v.y * v.y + v.z * v.z + v.w * v.w;
    #pragma unroll
    for (int o = 16; o; o >>= 1) sum += __shfl_xor_sync(0xffffffffu, sum, o);
    __shared__ float ws[8];
    __shared__ float s_inv;
    if ((t & 31) == 0) ws[t >> 5] = sum;
    __syncthreads();
    if (t == 0) {
        float tot = 0.f;
        #pragma unroll
        for (int i = 0; i < 8; i++) tot += ws[i];
        s_inv = (tot > 0.f) ? rsqrtf(tot) : 0.f;
    }
    __syncthreads();
    float inv = s_inv;
    float n[4] = {v.x * inv, v.y * inv, v.z * inv, v.w * inv};
    unsigned short* base = g_asp + b * 4 * 2048;
    #pragma unroll
    for (int j = 0; j < 4; j++) {
        __half h = __float2half(n[j]);
        __half l = __float2half(n[j] - __half2float(h));
        unsigned short hu = __half_as_ushort(h);
        unsigned short lu = __half_as_ushort(l);
        int e = 4 * t + j;
        base[e] = hu;                      base[e + 1024] = hu;
        base[2048 + ((e + 1023) & 2047)] = hu;
        base[2048 + ((e + 2047) & 2047)] = hu;
        base[4096 + e] = lu;               base[4096 + e + 1024] = lu;
        base[6144 + ((e + 1023) & 2047)] = lu;
        base[6144 + ((e + 2047) & 2047)] = lu;
    }
}

// E: normalize rows, single fp16, contiguous [row][k]
__global__ void esplit_kernel(const float* __restrict__ e) {
    int b = blockIdx.y, s = blockIdx.x, t = threadIdx.x;  // 256 threads
    size_t row = (size_t)b * SS + s;
    float4 v = ((const float4*)(e + row * DD))[t];
    float sum = v.x * v.x + v.y * v.y + v.z * v.z + v.w * v.w;
    #pragma unroll
    for (int o = 16; o; o >>= 1) sum += __shfl_xor_sync(0xffffffffu, sum, o);
    __shared__ float ws[8];
    __shared__ float s_inv;
    if ((t & 31) == 0) ws[t >> 5] = sum;
    __syncthreads();
    if (t == 0) {
        float tot = 0.f;
        #pragma unroll
        for (int i = 0; i < 8; i++) tot += ws[i];
        s_inv = (tot > 0.f) ? rsqrtf(tot) : 0.f;
    }
    __syncthreads();
    float inv = s_inv;
    float n[4] = {v.x * inv, v.y * inv, v.z * inv, v.w * inv};
    ushort4 ph;
    unsigned short* hp = &ph.x;
    #pragma unroll
    for (int j = 0; j < 4; j++)
        hp[j] = __half_as_ushort(__float2half(n[j]));
    ((ushort4*)(g_eh + row * DD))[t] = ph;
}

// ============================ GEMM kernel ============================
// out[b, s_base+m, i_base+n] = sum_k E[m][k] * Circ[n][k]
// E fp16, Circ fp16 hi+lo (2 products). CTA 256x128, 512 thr (16 warps,
// warp 64x32), k-chunk 64, 2-stage A ring, B built in smem from aspect.
#define ROWA 144                 // 128B payload + 16B pad
#define ROWBB 272                // 256B payload (hi128|lo128) + 16B pad
#define ASTG (256 * ROWA)        // 36864 per A stage
#define BSTG (128 * ROWBB)       // 34816 per B buffer
#define OFF_B (2 * ASTG)         // 73728
#define OFF_ASP (OFF_B + 2 * BSTG)   // 143360
#define SMEM_DYN (OFF_ASP + 16384)   // 159744
#define NCHUNK 16                // 1024 / 64

__global__ void __launch_bounds__(512, 1) gemm_kernel(float* __restrict__ out) {
    extern __shared__ __align__(128) char smem[];
    const uint32_t sbase = smem_u32(smem);
    const uint32_t sB = sbase + OFF_B;
    const uint32_t sAsp = sbase + OFF_ASP;

    const int b      = blockIdx.z;
    const int i_base = blockIdx.x * 128;
    const int s_base = blockIdx.y * 256;
    const int tid  = threadIdx.x;
    const int wid  = tid >> 5;
    const int lane = tid & 31;
    const int wm = wid & 3;      // 4 m-groups of 64
    const int wn = wid >> 2;     // 4 n-groups of 32

    // A loader: thread covers rows r0+64*i (i=0..3), fixed 16B segment tid&7
    const int r0  = tid >> 3;    // 0..63
    const int seg = tid & 7;
    const char* pA = (const char*)g_eh + ((size_t)b * SS + s_base + r0) * 2048 + seg * 16;
    const uint32_t drowA = sbase + (uint32_t)r0 * ROWA + seg * 16;

    // ldmatrix lane offsets
    const uint32_t a_lane = (uint32_t)(wm * 64 + (lane & 15)) * ROWA + (lane >> 4) * 16;
    const uint32_t b_lane = (uint32_t)(wn * 32 + (lane & 7) + 8 * (lane >> 4)) * ROWBB
                          + ((lane >> 3) & 1) * 16;

    // B build: this warp owns rows bn0..bn0+7
    const int bn0 = wn * 32 + wm * 8;

    float acc[4][4][4];
    #pragma unroll
    for (int mt = 0; mt < 4; mt++)
        #pragma unroll
        for (int nt = 0; nt < 4; nt++)
            #pragma unroll
            for (int j = 0; j < 4; j++) acc[mt][nt][j] = 0.f;

    #define LOAD_A(ST, KC) do {                                         \
        uint32_t so_ = (ST) * ASTG;                                     \
        size_t go_ = (size_t)(KC) * 128;                                \
        _Pragma("unroll")                                               \
        for (int i_ = 0; i_ < 4; i_++)                                  \
            cpasync16(drowA + so_ + i_ * (64 * ROWA),                   \
                      pA + go_ + (size_t)i_ * (64 * 2048));             \
        asm volatile("cp.async.commit_group;");                         \
    } while (0)

    // build 2 B rows (rr base RB) for chunk CN into buffer CN&1
    #define BUILD_B2(CN, RB) do {                                       \
        uint32_t bb_ = sB + ((CN) & 1) * BSTG;                          \
        int k0_ = (CN) * 64;                                            \
        _Pragma("unroll")                                               \
        for (int rr_ = (RB); rr_ < (RB) + 2; rr_++) {                   \
            int row_ = bn0 + rr_;                                       \
            int ig_ = i_base + row_;                                    \
            int p_ = ig_ & 1;                                           \
            uint32_t su_ = (uint32_t)((DD + k0_ - ig_ - p_) >> 1) * 4 + lane * 4; \
            uint32_t dst_ = bb_ + (uint32_t)row_ * ROWBB + lane * 4;    \
            sts32(dst_, lds32(sAsp + p_ * 4096 + su_));                 \
            sts32(dst_ + 128, lds32(sAsp + (2 + p_) * 4096 + su_));     \
        }                                                               \
    } while (0)

    // ---- prologue: aspect copies + A(0) in one group ----
    {
        const char* pAsp = (const char*)(g_asp + b * 4 * 2048);
        cpasync16(sAsp + tid * 16, pAsp + tid * 16);
        cpasync16(sAsp + (tid + 512) * 16, pAsp + (size_t)(tid + 512) * 16);
    }
    LOAD_A(0, 0);

    asm volatile("cp.async.wait_group 0;" ::: "memory");
    __syncthreads();
    BUILD_B2(0, 0); BUILD_B2(0, 2); BUILD_B2(0, 4); BUILD_B2(0, 6);

    #pragma unroll 2
    for (int c = 0; c < NCHUNK; c++) {
        if (c > 0) {
            asm volatile("cp.async.wait_group 0;" ::: "memory");
            __syncthreads();
        }
        if (c + 1 < NCHUNK) LOAD_A((c + 1) & 1, c + 1);

        const uint32_t sa = sbase + (c & 1) * ASTG;
        const uint32_t sb = sB + (c & 1) * BSTG;
        const bool more = (c + 1 < NCHUNK);

        #pragma unroll
        for (int kk = 0; kk < 4; kk++) {
            const uint32_t akb = (uint32_t)(kk * 32);   // A: contiguous k
            const uint32_t bkb = (uint32_t)(kk * 32);   // B: [hi 128 | lo 128]
            uint32_t aH[4][4], bH[2][4], bL[2][4];
            #pragma unroll
            for (int mt = 0; mt < 4; mt++)
                ldsm4(aH[mt], sa + a_lane + mt * 16 * ROWA + akb);
            #pragma unroll
            for (int p = 0; p < 2; p++)
                ldsm4(bH[p], sb + b_lane + p * 16 * ROWBB + bkb);
            #pragma unroll
            for (int p = 0; p < 2; p++)
                ldsm4(bL[p], sb + b_lane + p * 16 * ROWBB + bkb + 128);
            #pragma unroll
            for (int mt = 0; mt < 4; mt++)
                #pragma unroll
                for (int nt = 0; nt < 4; nt++)
                    mma16816(acc[mt][nt], aH[mt], &bH[nt >> 1][2 * (nt & 1)]);
            // interleave B-build for next chunk (2 rows per kk step)
            if (more) BUILD_B2(c + 1, kk * 2);
            #pragma unroll
            for (int mt = 0; mt < 4; mt++)
                #pragma unroll
                for (int nt = 0; nt < 4; nt++)
                    mma16816(acc[mt][nt], aH[mt], &bL[nt >> 1][2 * (nt & 1)]);
        }
    }

    // ---- epilogue: direct f32 stores ----
    #pragma unroll
    for (int mt = 0; mt < 4; mt++) {
        int rr = s_base + wm * 64 + mt * 16 + (lane >> 2);
        float* p0 = out + ((size_t)b * SS + rr) * DD + i_base + wn * 32 + (lane & 3) * 2;
        float* p1 = p0 + (size_t)8 * DD;
        #pragma unroll
        for (int nt = 0; nt < 4; nt++) {
            *(float2*)(p0 + nt * 8) = make_float2(acc[mt][nt][0], acc[mt][nt][1]);
            *(float2*)(p1 + nt * 8) = make_float2(acc[mt][nt][2], acc[mt][nt][3]);
        }
    }
}

// ============================ launch ============================
extern "C" void kernel_launch(void* const* d_in, const int* in_sizes, int n_in,
                              void* d_out, int out_size) {
    const float* emb = (const float*)d_in[0];   // (32, 512, 1024) f32
    const float* asp = (const float*)d_in[1];   // (32, 1024) f32
    float* out = (float*)d_out;                 // (32, 512, 1024) f32

    cudaFuncSetAttribute(gemm_kernel, cudaFuncAttributeMaxDynamicSharedMemorySize, SMEM_DYN);

    anorm_kernel<<<BB, 256>>>(asp);
    esplit_kernel<<<dim3(SS, BB), 256>>>(emb);
    gemm_kernel<<<dim3(DD / 128, SS / 256, BB), 512, SMEM_DYN>>>(out);
}

// round 10
// speedup vs baseline: 1.5113x; 1.0309x over previous
#include <cuda_runtime.h>
#include <cuda_fp16.h>
#include <cstdint>

#define BB 32
#define SS 512
#define DD 1024

// ---- device scratch (module-load allocated; no runtime allocs) ----
// E normalized fp16: [row][k] contiguous (2048B per row)
__device__ unsigned short g_eh[(size_t)BB * SS * DD];       // 32 MB
// aspect copies fp16: [b][buf(4: hi-p0, hi-p1, lo-p0, lo-p1)][2048 u16]
__device__ unsigned short g_asp[BB * 4 * 2048];             // 512 KB

// ============================ helpers ============================
__device__ __forceinline__ uint32_t smem_u32(const void* p) {
    uint32_t a;
    asm("{ .reg .u64 t; cvta.to.shared.u64 t, %1; cvt.u32.u64 %0, t; }" : "=r"(a) : "l"(p));
    return a;
}
__device__ __forceinline__ void cpasync16(uint32_t dst, const void* src) {
    asm volatile("cp.async.cg.shared.global [%0], [%1], 16;" :: "r"(dst), "l"(src));
}
__device__ __forceinline__ void ldsm4(uint32_t* r, uint32_t a) {
    asm volatile("ldmatrix.sync.aligned.m8n8.x4.shared.b16 {%0,%1,%2,%3}, [%4];"
                 : "=r"(r[0]), "=r"(r[1]), "=r"(r[2]), "=r"(r[3]) : "r"(a));
}
__device__ __forceinline__ void mma16816(float* c, const uint32_t* a, const uint32_t* b) {
    asm volatile(
        "mma.sync.aligned.m16n8k16.row.col.f32.f16.f16.f32 "
        "{%0,%1,%2,%3}, {%4,%5,%6,%7}, {%8,%9}, {%0,%1,%2,%3};"
        : "+f"(c[0]), "+f"(c[1]), "+f"(c[2]), "+f"(c[3])
        : "r"(a[0]), "r"(a[1]), "r"(a[2]), "r"(a[3]), "r"(b[0]), "r"(b[1]));
}
__device__ __forceinline__ uint32_t lds32(uint32_t a) {
    uint32_t v;
    asm volatile("ld.shared.b32 %0, [%1];" : "=r"(v) : "r"(a));
    return v;
}
__device__ __forceinline__ void sts32(uint32_t a, uint32_t v) {
    asm volatile("st.shared.b32 [%0], %1;" :: "r"(a), "r"(v));
}

// ============================ prep kernels ============================
// normalize aspect, split hi/lo fp16, write 4 parity copies
__global__ void anorm_kernel(const float* __restrict__ a) {
    int b = blockIdx.x, t = threadIdx.x;  // 256 threads
    float4 v = ((const float4*)(a + (size_t)b * DD))[t];
    float sum = v.x * v.x + v.y * v.y + v.z * v.z + v.w * v.w;
    #pragma unroll
    for (int o = 16; o; o >>= 1) sum += __shfl_xor_sync(0xffffffffu, sum, o);
    __shared__ float ws[8];
    __shared__ float s_inv;
    if ((t & 31) == 0) ws[t >> 5] = sum;
    __syncthreads();
    if (t == 0) {
        float tot = 0.f;
        #pragma unroll
        for (int i = 0; i < 8; i++) tot += ws[i];
        s_inv = (tot > 0.f) ? rsqrtf(tot) : 0.f;
    }
    __syncthreads();
    float inv = s_inv;
    float n[4] = {v.x * inv, v.y * inv, v.z * inv, v.w * inv};
    unsigned short* base = g_asp + b * 4 * 2048;
    #pragma unroll
    for (int j = 0; j < 4; j++) {
        __half h = __float2half(n[j]);
        __half l = __float2half(n[j] - __half2float(h));
        unsigned short hu = __half_as_ushort(h);
        unsigned short lu = __half_as_ushort(l);
        int e = 4 * t + j;
        base[e] = hu;                      base[e + 1024] = hu;
        base[2048 + ((e + 1023) & 2047)] = hu;
        base[2048 + ((e + 2047) & 2047)] = hu;
        base[4096 + e] = lu;               base[4096 + e + 1024] = lu;
        base[6144 + ((e + 1023) & 2047)] = lu;
        base[6144 + ((e + 2047) & 2047)] = lu;
    }
}

// E: normalize rows, single fp16, contiguous [row][k]
__global__ void esplit_kernel(const float* __restrict__ e) {
    int b = blockIdx.y, s = blockIdx.x, t = threadIdx.x;  // 256 threads
    size_t row = (size_t)b * SS + s;
    float4 v = ((const float4*)(e + row * DD))[t];
    float sum = v.x * v.x + v.y * v.y + v.z * v.z + v.w * v.w;
    #pragma unroll
    for (int o = 16; o; o >>= 1) sum += __shfl_xor_sync(0xffffffffu, sum, o);
    __shared__ float ws[8];
    __shared__ float s_inv;
    if ((t & 31) == 0) ws[t >> 5] = sum;
    __syncthreads();
    if (t == 0) {
        float tot = 0.f;
        #pragma unroll
        for (int i = 0; i < 8; i++) tot += ws[i];
        s_inv = (tot > 0.f) ? rsqrtf(tot) : 0.f;
    }
    __syncthreads();
    float inv = s_inv;
    float n[4] = {v.x * inv, v.y * inv, v.z * inv, v.w * inv};
    ushort4 ph;
    unsigned short* hp = &ph.x;
    #pragma unroll
    for (int j = 0; j < 4; j++)
        hp[j] = __half_as_ushort(__float2half(n[j]));
    ((ushort4*)(g_eh + row * DD))[t] = ph;
}

// ============================ GEMM kernel ============================
// out[b, s_base+m, i_base+n] = sum_k E[m][k] * Circ[n][k]
// E fp16, Circ fp16 hi+lo (2 products). CTA 128x128, 512 thr (16 warps,
// warp 32x32), k-chunk 64, 2-stage A ring, B built in smem from aspect.
#define ROWA 144                 // 128B payload + 16B pad
#define ROWBB 272                // 256B payload (hi128|lo128) + 16B pad
#define ASTG (128 * ROWA)        // 18432 per A stage
#define BSTG (128 * ROWBB)       // 34816 per B buffer
#define OFF_B (2 * ASTG)         // 36864
#define OFF_ASP (OFF_B + 2 * BSTG)   // 106496
#define SMEM_DYN (OFF_ASP + 16384)   // 122880
#define NCHUNK 16                // 1024 / 64

__global__ void __launch_bounds__(512, 1) gemm_kernel(float* __restrict__ out) {
    extern __shared__ __align__(128) char smem[];
    const uint32_t sbase = smem_u32(smem);
    const uint32_t sB = sbase + OFF_B;
    const uint32_t sAsp = sbase + OFF_ASP;

    const int b      = blockIdx.z;
    const int i_base = blockIdx.x * 128;
    const int s_base = blockIdx.y * 128;
    const int tid  = threadIdx.x;
    const int wid  = tid >> 5;
    const int lane = tid & 31;
    const int wm = wid & 3;      // 4 m-groups of 32
    const int wn = wid >> 2;     // 4 n-groups of 32

    // A loader: thread covers rows r0 and r0+64, fixed 16B segment tid&7
    const int r0  = tid >> 3;    // 0..63
    const int seg = tid & 7;
    const char* pA = (const char*)g_eh + ((size_t)b * SS + s_base + r0) * 2048 + seg * 16;
    const uint32_t drowA = sbase + (uint32_t)r0 * ROWA + seg * 16;

    // ldmatrix lane offsets
    const uint32_t a_lane = (uint32_t)(wm * 32 + (lane & 15)) * ROWA + (lane >> 4) * 16;
    const uint32_t b_lane = (uint32_t)(wn * 32 + (lane & 7) + 8 * (lane >> 4)) * ROWBB
                          + ((lane >> 3) & 1) * 16;

    // B build: this warp owns rows bn0..bn0+7
    const int bn0 = wid * 8;

    float acc[2][4][4];
    #pragma unroll
    for (int mt = 0; mt < 2; mt++)
        #pragma unroll
        for (int nt = 0; nt < 4; nt++)
            #pragma unroll
            for (int j = 0; j < 4; j++) acc[mt][nt][j] = 0.f;

    #define LOAD_A(ST, KC) do {                                         \
        uint32_t so_ = (ST) * ASTG;                                     \
        size_t go_ = (size_t)(KC) * 128;                                \
        cpasync16(drowA + so_, pA + go_);                               \
        cpasync16(drowA + so_ + 64 * ROWA, pA + go_ + (size_t)64 * 2048); \
        asm volatile("cp.async.commit_group;");                         \
    } while (0)

    // build 2 B rows (rr base RB) for chunk CN into buffer CN&1
    #define BUILD_B2(CN, RB) do {                                       \
        uint32_t bb_ = sB + ((CN) & 1) * BSTG;                          \
        int k0_ = (CN) * 64;                                            \
        _Pragma("unroll")                                               \
        for (int rr_ = (RB); rr_ < (RB) + 2; rr_++) {                   \
            int row_ = bn0 + rr_;                                       \
            int ig_ = i_base + row_;                                    \
            int p_ = ig_ & 1;                                           \
            uint32_t su_ = (uint32_t)((DD + k0_ - ig_ - p_) >> 1) * 4 + lane * 4; \
            uint32_t dst_ = bb_ + (uint32_t)row_ * ROWBB + lane * 4;    \
            sts32(dst_, lds32(sAsp + p_ * 4096 + su_));                 \
            sts32(dst_ + 128, lds32(sAsp + (2 + p_) * 4096 + su_));     \
        }                                                               \
    } while (0)

    // ---- prologue: aspect copies + A(0) in one group ----
    {
        const char* pAsp = (const char*)(g_asp + b * 4 * 2048);
        cpasync16(sAsp + tid * 16, pAsp + tid * 16);
        cpasync16(sAsp + (tid + 512) * 16, pAsp + (size_t)(tid + 512) * 16);
    }
    LOAD_A(0, 0);

    asm volatile("cp.async.wait_group 0;" ::: "memory");
    __syncthreads();
    BUILD_B2(0, 0); BUILD_B2(0, 2); BUILD_B2(0, 4); BUILD_B2(0, 6);
    __syncthreads();   // publish chunk-0 B build before first ldsm

    #pragma unroll 2
    for (int c = 0; c < NCHUNK; c++) {
        if (c > 0) {
            asm volatile("cp.async.wait_group 0;" ::: "memory");
            __syncthreads();
        }
        if (c + 1 < NCHUNK) LOAD_A((c + 1) & 1, c + 1);

        const uint32_t sa = sbase + (c & 1) * ASTG;
        const uint32_t sb = sB + (c & 1) * BSTG;
        const bool more = (c + 1 < NCHUNK);

        #pragma unroll
        for (int kk = 0; kk < 4; kk++) {
            const uint32_t akb = (uint32_t)(kk * 32);   // A: contiguous k
            const uint32_t bkb = (uint32_t)(kk * 32);   // B: [hi 128 | lo 128]
            uint32_t aH[2][4], bH[2][4], bL[2][4];
            #pragma unroll
            for (int mt = 0; mt < 2; mt++)
                ldsm4(aH[mt], sa + a_lane + mt * 16 * ROWA + akb);
            #pragma unroll
            for (int p = 0; p < 2; p++)
                ldsm4(bH[p], sb + b_lane + p * 16 * ROWBB + bkb);
            #pragma unroll
            for (int p = 0; p < 2; p++)
                ldsm4(bL[p], sb + b_lane + p * 16 * ROWBB + bkb + 128);
            #pragma unroll
            for (int mt = 0; mt < 2; mt++)
                #pragma unroll
                for (int nt = 0; nt < 4; nt++)
                    mma16816(acc[mt][nt], aH[mt], &bH[nt >> 1][2 * (nt & 1)]);
            // interleave B-build for next chunk (2 rows per kk step)
            if (more) BUILD_B2(c + 1, kk * 2);
            #pragma unroll
            for (int mt = 0; mt < 2; mt++)
                #pragma unroll
                for (int nt = 0; nt < 4; nt++)
                    mma16816(acc[mt][nt], aH[mt], &bL[nt >> 1][2 * (nt & 1)]);
        }
    }

    // ---- epilogue: direct f32 stores ----
    #pragma unroll
    for (int mt = 0; mt < 2; mt++) {
        int rr = s_base + wm * 32 + mt * 16 + (lane >> 2);
        float* p0 = out + ((size_t)b * SS + rr) * DD + i_base + wn * 32 + (lane & 3) * 2;
        float* p1 = p0 + (size_t)8 * DD;
        #pragma unroll
        for (int nt = 0; nt < 4; nt++) {
            *(float2*)(p0 + nt * 8) = make_float2(acc[mt][nt][0], acc[mt][nt][1]);
            *(float2*)(p1 + nt * 8) = make_float2(acc[mt][nt][2], acc[mt][nt][3]);
        }
    }
}

// ============================ launch ============================
extern "C" void kernel_launch(void* const* d_in, const int* in_sizes, int n_in,
                              void* d_out, int out_size) {
    const float* emb = (const float*)d_in[0];   // (32, 512, 1024) f32
    const float* asp = (const float*)d_in[1];   // (32, 1024) f32
    float* out = (float*)d_out;                 // (32, 512, 1024) f32

    cudaFuncSetAttribute(gemm_kernel, cudaFuncAttributeMaxDynamicSharedMemorySize, SMEM_DYN);

    anorm_kernel<<<BB, 256>>>(asp);
    esplit_kernel<<<dim3(SS, BB), 256>>>(emb);
    gemm_kernel<<<dim3(DD / 128, SS / 128, BB), 512, SMEM_DYN>>>(out);
}